// round 8
// baseline (speedup 1.0000x reference)
#include <cuda_runtime.h>

// PlasticNet: T=64 steps, B=32, I=128, H=256, clip=2.0
// out = [ ys (T*B*H) | h_f (B*H) | hebb_f (B*H*H) ]  float32
//
// 32 clusters of 4 CTAs (one per sample). CTA c owns presynaptic rows
// [c*64, c*64+64). Thread t owns column t: 64 hebb/w/alpha scalars in regs,
// packed as 32 f32x2 pairs (fma.rn.f32x2; clip scalar on the halves).
// Per step: push 256-wide rec partials into peers' SMEM (DSMEM), then one
// hardware cluster barrier (arrive/wait split) orders delivery.

static constexpr int kT = 64;
static constexpr int kB = 32;
static constexpr int kI = 128;
static constexpr int kH = 256;
static constexpr int kRows = 64;
static constexpr int kNCTA = kB * 4;
static constexpr int kThreads = 256;
static constexpr int kXwiRows = 4;                 // rows per CTA in xwi kernel

typedef unsigned long long ull;

__device__ float g_xwi[kT * kB * kH];              // x@Wi + bi, precomputed

// ---------------------------------------------------------------------------
// Kernel 1: xwi[row,k] = sum_i x[row,i]*Wi[i,k] + bi[k], 4 rows per CTA.
// ---------------------------------------------------------------------------
__global__ void xwi_kernel(const float* __restrict__ x,
                           const float* __restrict__ Wi,
                           const float* __restrict__ bi) {
    __shared__ __align__(16) float xs[kXwiRows][kI];
    const int row0 = blockIdx.x * kXwiRows;
    const int t = threadIdx.x;
    // stage 4 rows of x (512 floats = 128 float4)
    if (t < 128)
        reinterpret_cast<float4*>(xs)[t] =
            reinterpret_cast<const float4*>(x + row0 * kI)[t];
    __syncthreads();
    float a0 = bi[t], a1 = a0, a2 = a0, a3 = a0;
#pragma unroll 8
    for (int ii = 0; ii < kI / 4; ++ii) {
        const float4 x0 = *reinterpret_cast<const float4*>(&xs[0][4 * ii]);
        const float4 x1 = *reinterpret_cast<const float4*>(&xs[1][4 * ii]);
        const float4 x2 = *reinterpret_cast<const float4*>(&xs[2][4 * ii]);
        const float4 x3 = *reinterpret_cast<const float4*>(&xs[3][4 * ii]);
        const float w0 = __ldg(&Wi[(4 * ii + 0) * kH + t]);
        const float w1 = __ldg(&Wi[(4 * ii + 1) * kH + t]);
        const float w2 = __ldg(&Wi[(4 * ii + 2) * kH + t]);
        const float w3 = __ldg(&Wi[(4 * ii + 3) * kH + t]);
        a0 = fmaf(x0.x, w0, a0); a0 = fmaf(x0.y, w1, a0);
        a0 = fmaf(x0.z, w2, a0); a0 = fmaf(x0.w, w3, a0);
        a1 = fmaf(x1.x, w0, a1); a1 = fmaf(x1.y, w1, a1);
        a1 = fmaf(x1.z, w2, a1); a1 = fmaf(x1.w, w3, a1);
        a2 = fmaf(x2.x, w0, a2); a2 = fmaf(x2.y, w1, a2);
        a2 = fmaf(x2.z, w2, a2); a2 = fmaf(x2.w, w3, a2);
        a3 = fmaf(x3.x, w0, a3); a3 = fmaf(x3.y, w1, a3);
        a3 = fmaf(x3.z, w2, a3); a3 = fmaf(x3.w, w3, a3);
    }
    g_xwi[(row0 + 0) * kH + t] = a0;
    g_xwi[(row0 + 1) * kH + t] = a1;
    g_xwi[(row0 + 2) * kH + t] = a2;
    g_xwi[(row0 + 3) * kH + t] = a3;
}

// ---------------------------------------------------------------------------
// PTX helpers
// ---------------------------------------------------------------------------
__device__ __forceinline__ unsigned smem_u32(const void* p) {
    return (unsigned)__cvta_generic_to_shared(p);
}
__device__ __forceinline__ unsigned mapa_u32(unsigned addr, unsigned rank) {
    unsigned o;
    asm("mapa.shared::cluster.u32 %0, %1, %2;" : "=r"(o) : "r"(addr), "r"(rank));
    return o;
}
__device__ __forceinline__ void st_cluster_f32(unsigned addr, float v) {
    asm volatile("st.shared::cluster.f32 [%0], %1;" :: "r"(addr), "f"(v) : "memory");
}
__device__ __forceinline__ void cluster_arrive() {
    asm volatile("barrier.cluster.arrive.aligned;" ::: "memory");
}
__device__ __forceinline__ void cluster_wait() {
    asm volatile("barrier.cluster.wait.aligned;" ::: "memory");
}

// ---- f32x2 packed math (PTX has fma/add/mul only; clip done on halves) ----
__device__ __forceinline__ ull pack2(float lo, float hi) {
    ull r; asm("mov.b64 %0, {%1, %2};" : "=l"(r) : "f"(lo), "f"(hi)); return r;
}
__device__ __forceinline__ void unpack2(ull v, float& lo, float& hi) {
    asm("mov.b64 {%0, %1}, %2;" : "=f"(lo), "=f"(hi) : "l"(v));
}
__device__ __forceinline__ ull fma2(ull a, ull b, ull c) {
    ull d; asm("fma.rn.f32x2 %0, %1, %2, %3;" : "=l"(d) : "l"(a), "l"(b), "l"(c));
    return d;
}
__device__ __forceinline__ ull clip2(ull v) {
    float lo, hi;
    unpack2(v, lo, hi);
    lo = fminf(fmaxf(lo, -2.f), 2.f);
    hi = fminf(fmaxf(hi, -2.f), 2.f);
    return pack2(lo, hi);
}

// ---- fast tanh: 2 MUFU + few flops, ~1e-6 error (vs 1e-3 threshold) ----
__device__ __forceinline__ float ftanh(float x) {
    const float ax = fabsf(x);
    const float e = exp2f(-2.88539008f * ax);      // exp(-2|x|), MUFU.EX2
    const float r = __fdividef(1.f - e, 1.f + e);  // MUFU.RCP + mul
    return copysignf(r, x);
}

// ---------------------------------------------------------------------------
__global__ void __launch_bounds__(kThreads, 1) __cluster_dims__(4, 1, 1)
plastic_kernel(const float* __restrict__ w,
               const float* __restrict__ alpha,
               const float* __restrict__ Wm,
               const float* __restrict__ bm,
               const float* __restrict__ Wf,
               const float* __restrict__ bf,
               float* __restrict__ out) {
    const int b = blockIdx.x >> 2;
    const int c = blockIdx.x & 3;      // cluster ctarank
    const int t = threadIdx.x;
    const int lane = t & 31;
    const int wid = t >> 5;
    const int i0 = c * kRows;

    // Register state, packed by presynaptic-row pairs: pair j = rows i0+2j, i0+2j+1
    ull wv2[32], av2[32], hb2[32];
#pragma unroll
    for (int j = 0; j < 32; ++j) {
        wv2[j] = pack2(__ldg(&w[(i0 + 2 * j) * kH + t]),
                       __ldg(&w[(i0 + 2 * j + 1) * kH + t]));
        av2[j] = pack2(__ldg(&alpha[(i0 + 2 * j) * kH + t]),
                       __ldg(&alpha[(i0 + 2 * j + 1) * kH + t]));
        hb2[j] = 0ull;
    }
    const float wf_t = __ldg(&Wf[t]);
    const float bf_t = __ldg(&bf[t]);
    const float wm_t = __ldg(&Wm[t]);
    const float bm0 = __ldg(&bm[0]);

    __shared__ __align__(16) float hbuf[2][kH];       // h double buffer
    __shared__ __align__(16) float recv[2][4][kH];    // cluster partials, dbl buf
    __shared__ __align__(16) float wpart[8];          // per-warp eta partials

    hbuf[0][t] = 0.f;   // h_{-1} = 0
    __syncthreads();
    cluster_arrive();   // peers' smem live before any remote store
    cluster_wait();

    // DSMEM push addresses for the 3 peers (both parities)
    unsigned pr_addr[2][3];
#pragma unroll
    for (int p = 0; p < 2; ++p) {
        const unsigned lr = smem_u32(&recv[p][c][t]);
#pragma unroll
        for (int d = 1; d < 4; ++d)
            pr_addr[p][d - 1] = mapa_u32(lr, (unsigned)((c + d) & 3));
    }

    float* __restrict__ ys = out;
    float* __restrict__ hf = out + kT * kB * kH;
    float* __restrict__ hebbf = out + kT * kB * kH + kB * kH;

    // step 0: h_{-1}=0 -> rec=0 -> h = tanh(xwi[0])
    float h_cur = ftanh(__ldg(&g_xwi[b * kH + t]));

    for (int step = 0; step < kT; ++step) {
        const int par = step & 1;
        const float* __restrict__ hp = hbuf[par];        // h_{step-1}
        float* __restrict__ hn = hbuf[par ^ 1];          // h_step

        // prefetch next step's xwi early (hides L2 latency under the sweep)
        float xw_next = 0.f;
        if (step < kT - 1)
            xw_next = __ldg(&g_xwi[((step + 1) * kB + b) * kH + t]);

        hn[t] = h_cur;
        // eta partial: warp-level reduce of h.Wm, pre-sync
        float s = h_cur * wm_t;
#pragma unroll
        for (int off = 16; off; off >>= 1)
            s += __shfl_xor_sync(0xffffffffu, s, off);
        if (lane == 0) wpart[wid] = s;
        if (c == 0) ys[(step * kB + b) * kH + t] = h_cur;
        __syncthreads();

        // ---- eta = tanh(h . Wm + bm) ----
        const float4 wp0 = *reinterpret_cast<const float4*>(&wpart[0]);
        const float4 wp1 = *reinterpret_cast<const float4*>(&wpart[4]);
        const float eta = ftanh(((wp0.x + wp0.y) + (wp0.z + wp0.w)) +
                                ((wp1.x + wp1.y) + (wp1.z + wp1.w)) + bm0);
        const float v = fmaf(eta, wf_t, bf_t) * h_cur;    // me_t * h_t
        const ull vv = pack2(v, v);

        // ---- fused sweep: hebb = clip(hebb + v*hp), pr += hn*(w + a*hebb) ----
        ull prA = 0ull, prB = 0ull;
#pragma unroll
        for (int jj = 0; jj < 16; ++jj) {
            const float4 hp4 = *reinterpret_cast<const float4*>(&hp[i0 + 4 * jj]);
            const float4 hn4 = *reinterpret_cast<const float4*>(&hn[i0 + 4 * jj]);
            const ull hpa = pack2(hp4.x, hp4.y), hpb = pack2(hp4.z, hp4.w);
            const ull hna = pack2(hn4.x, hn4.y), hnb = pack2(hn4.z, hn4.w);
            const int j = 2 * jj;
            hb2[j]     = clip2(fma2(vv, hpa, hb2[j]));
            prA = fma2(hna, fma2(av2[j], hb2[j], wv2[j]), prA);
            hb2[j + 1] = clip2(fma2(vv, hpb, hb2[j + 1]));
            prB = fma2(hnb, fma2(av2[j + 1], hb2[j + 1], wv2[j + 1]), prB);
        }

        if (step < kT - 1) {
            float pa, pb, pc, pd;
            unpack2(prA, pa, pb);
            unpack2(prB, pc, pd);
            const float pr = (pa + pb) + (pc + pd);
            const int np = par ^ 1;
            // push partial to self + 3 peers
            recv[np][c][t] = pr;
            st_cluster_f32(pr_addr[np][0], pr);
            st_cluster_f32(pr_addr[np][1], pr);
            st_cluster_f32(pr_addr[np][2], pr);
            // hardware cluster barrier; arrive's release orders the pushes
            cluster_arrive();
            cluster_wait();
            const float hsum = (recv[np][0][t] + recv[np][1][t]) +
                               (recv[np][2][t] + recv[np][3][t]);
            h_cur = ftanh(xw_next + hsum);
        }
    }

    // ---- final outputs ----
    if (c == 0) hf[b * kH + t] = h_cur;    // h at step T-1
#pragma unroll
    for (int j = 0; j < 32; ++j) {
        float lo, hi;
        unpack2(hb2[j], lo, hi);
        hebbf[(size_t)b * kH * kH + (i0 + 2 * j) * kH + t] = lo;
        hebbf[(size_t)b * kH * kH + (i0 + 2 * j + 1) * kH + t] = hi;
    }
}

// ---------------------------------------------------------------------------
extern "C" void kernel_launch(void* const* d_in, const int* in_sizes, int n_in,
                              void* d_out, int out_size) {
    const float* x     = (const float*)d_in[0];
    const float* Wi    = (const float*)d_in[1];
    const float* bi    = (const float*)d_in[2];
    const float* w     = (const float*)d_in[3];
    const float* alpha = (const float*)d_in[4];
    const float* Wm    = (const float*)d_in[5];
    const float* bm    = (const float*)d_in[6];
    const float* Wf    = (const float*)d_in[7];
    const float* bf    = (const float*)d_in[8];
    float* out = (float*)d_out;

    xwi_kernel<<<(kT * kB) / kXwiRows, kThreads>>>(x, Wi, bi);
    plastic_kernel<<<kNCTA, kThreads>>>(w, alpha, Wm, bm, Wf, bf, out);
}

// round 10
// speedup vs baseline: 1.1482x; 1.1482x over previous
#include <cuda_runtime.h>

// PlasticNet: T=64 steps, B=32, I=128, H=256, clip=2.0
// out = [ ys (T*B*H) | h_f (B*H) | hebb_f (B*H*H) ]  float32
//
// Single kernel: 32 clusters of 4 CTAs (one per sample). CTA c owns
// presynaptic rows [c*64, c*64+64); thread t owns column t.
// Prologue: CTA c computes xwi = x@Wi+bi for steps [16c,16c+16) of its sample.
// g_xwi is written/read cross-CTA -> coherent ld.global.cg (__ldcg) ONLY; the
// cluster barrier's release/acquire orders it.
// hebb kept in saturated space hbs=(hebb+2)/4 in [0,1]: the clip becomes a
// free .sat modifier on FFMA. rec uses w'=w-2a, a'=4a: w+a*hebb = w'+a'*hbs.
// Per step: push 256-wide rec partials into peers' SMEM (DSMEM), then one
// hardware cluster barrier (arrive/wait split) orders delivery.

static constexpr int kT = 64;
static constexpr int kB = 32;
static constexpr int kI = 128;
static constexpr int kH = 256;
static constexpr int kRows = 64;
static constexpr int kNCTA = kB * 4;
static constexpr int kThreads = 256;

typedef unsigned long long ull;

__device__ float g_xwi[kT * kB * kH];              // x@Wi + bi

// ---------------------------------------------------------------------------
// PTX helpers
// ---------------------------------------------------------------------------
__device__ __forceinline__ unsigned smem_u32(const void* p) {
    return (unsigned)__cvta_generic_to_shared(p);
}
__device__ __forceinline__ unsigned mapa_u32(unsigned addr, unsigned rank) {
    unsigned o;
    asm("mapa.shared::cluster.u32 %0, %1, %2;" : "=r"(o) : "r"(addr), "r"(rank));
    return o;
}
__device__ __forceinline__ void st_cluster_f32(unsigned addr, float v) {
    asm volatile("st.shared::cluster.f32 [%0], %1;" :: "r"(addr), "f"(v) : "memory");
}
__device__ __forceinline__ void cluster_arrive() {
    asm volatile("barrier.cluster.arrive.aligned;" ::: "memory");
}
__device__ __forceinline__ void cluster_wait() {
    asm volatile("barrier.cluster.wait.aligned;" ::: "memory");
}

// ---- f32x2 packed math ----
__device__ __forceinline__ ull pack2(float lo, float hi) {
    ull r; asm("mov.b64 %0, {%1, %2};" : "=l"(r) : "f"(lo), "f"(hi)); return r;
}
__device__ __forceinline__ void unpack2(ull v, float& lo, float& hi) {
    asm("mov.b64 {%0, %1}, %2;" : "=f"(lo), "=f"(hi) : "l"(v));
}
__device__ __forceinline__ ull fma2(ull a, ull b, ull c) {
    ull d; asm("fma.rn.f32x2 %0, %1, %2, %3;" : "=l"(d) : "l"(a), "l"(b), "l"(c));
    return d;
}
// saturating scalar fma: clamps result to [0,1] as a free output modifier
__device__ __forceinline__ float fma_sat(float a, float b, float c) {
    float d; asm("fma.rn.sat.f32 %0, %1, %2, %3;" : "=f"(d) : "f"(a), "f"(b), "f"(c));
    return d;
}

// ---------------------------------------------------------------------------
__global__ void __launch_bounds__(kThreads, 1) __cluster_dims__(4, 1, 1)
plastic_kernel(const float* __restrict__ x,
               const float* __restrict__ Wi,
               const float* __restrict__ bi,
               const float* __restrict__ w,
               const float* __restrict__ alpha,
               const float* __restrict__ Wm,
               const float* __restrict__ bm,
               const float* __restrict__ Wf,
               const float* __restrict__ bf,
               float* __restrict__ out) {
    const int b = blockIdx.x >> 2;
    const int c = blockIdx.x & 3;      // cluster ctarank
    const int t = threadIdx.x;
    const int lane = t & 31;
    const int wid = t >> 5;
    const int i0 = c * kRows;

    __shared__ __align__(16) float hbuf[2][kH];       // h double buffer
    __shared__ __align__(16) float recv[2][4][kH];    // cluster partials, dbl buf
    __shared__ __align__(16) float wpart[8];          // per-warp eta partials

    // ======== prologue: xwi for steps [16c, 16c+16) of sample b ========
    {
        float* xs = reinterpret_cast<float*>(recv);   // 16*128 floats = 8KB alias
        const float bi_t = __ldg(&bi[t]);
        const int s0 = c * 16;
        if (t < kI) {
#pragma unroll
            for (int s = 0; s < 16; ++s)
                xs[s * kI + t] = __ldg(&x[((s0 + s) * kB + b) * kI + t]);
        }
        __syncthreads();
        float acc[16];
#pragma unroll
        for (int s = 0; s < 16; ++s) acc[s] = bi_t;
#pragma unroll 4
        for (int ib = 0; ib < kI; ib += 4) {
            const float q0 = __ldg(&Wi[(ib + 0) * kH + t]);
            const float q1 = __ldg(&Wi[(ib + 1) * kH + t]);
            const float q2 = __ldg(&Wi[(ib + 2) * kH + t]);
            const float q3 = __ldg(&Wi[(ib + 3) * kH + t]);
#pragma unroll
            for (int s = 0; s < 16; ++s) {
                const float4 xv = *reinterpret_cast<const float4*>(&xs[s * kI + ib]);
                acc[s] = fmaf(xv.w, q3, fmaf(xv.z, q2,
                         fmaf(xv.y, q1, fmaf(xv.x, q0, acc[s]))));
            }
        }
#pragma unroll
        for (int s = 0; s < 16; ++s)
            g_xwi[((s0 + s) * kB + b) * kH + t] = acc[s];
    }

    // ======== register state: rows i0+2j, i0+2j+1, column t ========
    // wv2 = (w - 2a) pair, av2 = (4a) pair, hbs = (hebb+2)/4 in [0,1]
    ull wv2[32], av2[32];
    float hbL[32], hbH[32];
#pragma unroll
    for (int j = 0; j < 32; ++j) {
        const float w0 = __ldg(&w[(i0 + 2 * j) * kH + t]);
        const float w1 = __ldg(&w[(i0 + 2 * j + 1) * kH + t]);
        const float a0 = __ldg(&alpha[(i0 + 2 * j) * kH + t]);
        const float a1 = __ldg(&alpha[(i0 + 2 * j + 1) * kH + t]);
        wv2[j] = pack2(fmaf(-2.f, a0, w0), fmaf(-2.f, a1, w1));
        av2[j] = pack2(4.f * a0, 4.f * a1);
        hbL[j] = 0.5f;   // hebb = 0
        hbH[j] = 0.5f;
    }
    const float wf_t = __ldg(&Wf[t]);
    const float bf_t = __ldg(&bf[t]);
    const float wm_t = __ldg(&Wm[t]);
    const float bm0 = __ldg(&bm[0]);

    hbuf[0][t] = 0.f;   // h_{-1} = 0
    __syncthreads();
    // orders: peers' smem live, AND all 4 CTAs' g_xwi stores visible to
    // subsequent coherent (__ldcg) loads within the cluster
    cluster_arrive();
    cluster_wait();

    // DSMEM push addresses for the 3 peers (both parities)
    unsigned pr_addr[2][3];
#pragma unroll
    for (int p = 0; p < 2; ++p) {
        const unsigned lr = smem_u32(&recv[p][c][t]);
#pragma unroll
        for (int d = 1; d < 4; ++d)
            pr_addr[p][d - 1] = mapa_u32(lr, (unsigned)((c + d) & 3));
    }

    float* __restrict__ ys = out;
    float* __restrict__ hf = out + kT * kB * kH;
    float* __restrict__ hebbf = out + kT * kB * kH + kB * kH;

    // step 0: h_{-1}=0 -> rec=0 -> h = tanh(xwi[0])  (coherent load!)
    float h_cur = tanhf(__ldcg(&g_xwi[b * kH + t]));

    for (int step = 0; step < kT; ++step) {
        const int par = step & 1;
        const float* __restrict__ hp = hbuf[par];        // h_{step-1}
        float* __restrict__ hn = hbuf[par ^ 1];          // h_step

        // prefetch next step's xwi early (coherent; hides L2 latency)
        float xw_next = 0.f;
        if (step < kT - 1)
            xw_next = __ldcg(&g_xwi[((step + 1) * kB + b) * kH + t]);

        hn[t] = h_cur;
        // eta partial: warp-level reduce of h.Wm, pre-sync
        float s = h_cur * wm_t;
#pragma unroll
        for (int off = 16; off; off >>= 1)
            s += __shfl_xor_sync(0xffffffffu, s, off);
        if (lane == 0) wpart[wid] = s;
        if (c == 0) ys[(step * kB + b) * kH + t] = h_cur;
        __syncthreads();

        // ---- eta = tanh(h . Wm + bm) ----
        const float4 wp0 = *reinterpret_cast<const float4*>(&wpart[0]);
        const float4 wp1 = *reinterpret_cast<const float4*>(&wpart[4]);
        const float eta = tanhf(((wp0.x + wp0.y) + (wp0.z + wp0.w)) +
                                ((wp1.x + wp1.y) + (wp1.z + wp1.w)) + bm0);
        const float v = fmaf(eta, wf_t, bf_t) * h_cur;    // me_t * h_t
        const float v4 = 0.25f * v;                       // exact scale

        // ---- fused sweep: hbs = sat(hbs + v4*hp), pr += hn*(w' + a'*hbs) ----
        ull prA = 0ull, prB = 0ull;
#pragma unroll
        for (int jj = 0; jj < 16; ++jj) {
            const float4 hp4 = *reinterpret_cast<const float4*>(&hp[i0 + 4 * jj]);
            const float4 hn4 = *reinterpret_cast<const float4*>(&hn[i0 + 4 * jj]);
            const int j = 2 * jj;
            hbL[j]     = fma_sat(v4, hp4.x, hbL[j]);
            hbH[j]     = fma_sat(v4, hp4.y, hbH[j]);
            hbL[j + 1] = fma_sat(v4, hp4.z, hbL[j + 1]);
            hbH[j + 1] = fma_sat(v4, hp4.w, hbH[j + 1]);
            prA = fma2(pack2(hn4.x, hn4.y),
                       fma2(av2[j], pack2(hbL[j], hbH[j]), wv2[j]), prA);
            prB = fma2(pack2(hn4.z, hn4.w),
                       fma2(av2[j + 1], pack2(hbL[j + 1], hbH[j + 1]), wv2[j + 1]), prB);
        }

        if (step < kT - 1) {
            float pa, pb, pc, pd;
            unpack2(prA, pa, pb);
            unpack2(prB, pc, pd);
            const float pr = (pa + pb) + (pc + pd);
            const int np = par ^ 1;
            // push partial to self + 3 peers
            recv[np][c][t] = pr;
            st_cluster_f32(pr_addr[np][0], pr);
            st_cluster_f32(pr_addr[np][1], pr);
            st_cluster_f32(pr_addr[np][2], pr);
            // hardware cluster barrier; arrive's release orders the pushes
            cluster_arrive();
            cluster_wait();
            const float hsum = (recv[np][0][t] + recv[np][1][t]) +
                               (recv[np][2][t] + recv[np][3][t]);
            h_cur = tanhf(xw_next + hsum);
        }
    }

    // ---- final outputs (hebb = 4*hbs - 2) ----
    if (c == 0) hf[b * kH + t] = h_cur;    // h at step T-1
#pragma unroll
    for (int j = 0; j < 32; ++j) {
        hebbf[(size_t)b * kH * kH + (i0 + 2 * j) * kH + t] =
            fmaf(4.f, hbL[j], -2.f);
        hebbf[(size_t)b * kH * kH + (i0 + 2 * j + 1) * kH + t] =
            fmaf(4.f, hbH[j], -2.f);
    }
}

// ---------------------------------------------------------------------------
extern "C" void kernel_launch(void* const* d_in, const int* in_sizes, int n_in,
                              void* d_out, int out_size) {
    const float* x     = (const float*)d_in[0];
    const float* Wi    = (const float*)d_in[1];
    const float* bi    = (const float*)d_in[2];
    const float* w     = (const float*)d_in[3];
    const float* alpha = (const float*)d_in[4];
    const float* Wm    = (const float*)d_in[5];
    const float* bm    = (const float*)d_in[6];
    const float* Wf    = (const float*)d_in[7];
    const float* bf    = (const float*)d_in[8];
    float* out = (float*)d_out;

    plastic_kernel<<<kNCTA, kThreads>>>(x, Wi, bi, w, alpha, Wm, bm, Wf, bf, out);
}